// round 2
// baseline (speedup 1.0000x reference)
#include <cuda_runtime.h>
#include <cstdint>

#define TT 2048
#define DIMX 1024
#define HIDX 4096
#define NEXP 8
#define NR 7
#define ALPHAF 2.0f

#define BM 128
#define BN_UG 64
#define BN_D 128
#define BKK 16

// -------- device scratch (no allocations allowed) --------
__device__ int g_count[NEXP];
__device__ int g_offset[NR];
__device__ int g_list[NR * TT];
__device__ float g_wtok[TT];
__device__ float g_hr[(size_t)TT * HIDX];  // routed h, rows = offset[e]+slot
__device__ float g_hs[(size_t)TT * HIDX];  // shared h, rows = token

__device__ __forceinline__ float to_tf32(float x) {
    float r;
    asm("cvt.rna.tf32.f32 %0, %1;" : "=f"(r) : "f"(x));
    return r;
}

__device__ __forceinline__ void mma_tf32(float* d, const uint32_t* a, const uint32_t* b) {
    asm volatile(
        "mma.sync.aligned.m16n8k8.row.col.f32.tf32.tf32.f32 "
        "{%0,%1,%2,%3}, {%4,%5,%6,%7}, {%8,%9}, {%0,%1,%2,%3};"
        : "+f"(d[0]), "+f"(d[1]), "+f"(d[2]), "+f"(d[3])
        : "r"(a[0]), "r"(a[1]), "r"(a[2]), "r"(a[3]), "r"(b[0]), "r"(b[1]));
}

// -------- init: zero group counts --------
__global__ void init_kernel() {
    if (threadIdx.x < NEXP) g_count[threadIdx.x] = 0;
}

// -------- router: fp32 logits, softmax, top-1, build lists --------
__global__ void router_kernel(const float* __restrict__ x, const float* __restrict__ wr) {
    __shared__ float sw[DIMX * NEXP];  // 32KB
    for (int i = threadIdx.x; i < DIMX * NEXP; i += blockDim.x) sw[i] = wr[i];
    __syncthreads();
    const int warp = threadIdx.x >> 5;
    const int lane = threadIdx.x & 31;
    const int tok = blockIdx.x * 8 + warp;
    if (tok >= TT) return;
    const float* xr = x + (size_t)tok * DIMX;
    float acc[NEXP];
#pragma unroll
    for (int e = 0; e < NEXP; ++e) acc[e] = 0.f;
    for (int k = lane; k < DIMX; k += 32) {
        float xv = xr[k];
#pragma unroll
        for (int e = 0; e < NEXP; ++e) acc[e] += xv * sw[k * NEXP + e];
    }
#pragma unroll
    for (int e = 0; e < NEXP; ++e)
#pragma unroll
        for (int o = 16; o; o >>= 1) acc[e] += __shfl_xor_sync(~0u, acc[e], o);
    if (lane == 0) {
        float m = acc[0];
        int idx = 0;
#pragma unroll
        for (int e = 1; e < NEXP; ++e)
            if (acc[e] > m) { m = acc[e]; idx = e; }
        float s = 0.f;
#pragma unroll
        for (int e = 0; e < NEXP; ++e) s += expf(acc[e] - m);
        float p = 1.0f / s;  // prob of argmax
        g_wtok[tok] = ALPHAF * p;
        if (idx < NR) {
            int slot = atomicAdd(&g_count[idx], 1);
            g_list[idx * TT + slot] = tok;
        }
    }
}

// -------- tiny exclusive prefix over counts --------
__global__ void offsets_kernel() {
    if (threadIdx.x == 0) {
        int off = 0;
        for (int e = 0; e < NR; ++e) { g_offset[e] = off; off += g_count[e]; }
    }
}

// -------- grouped up+gate GEMM with fused SwiGLU epilogue --------
__global__ __launch_bounds__(256, 2) void upgate_kernel(
    const float* __restrict__ x,
    const float* __restrict__ w_up, const float* __restrict__ w_gate,
    const float* __restrict__ ws_up, const float* __restrict__ ws_gate) {
    const int g = blockIdx.z;
    int n_rows, base;
    const float *Wu, *Wg;
    float* H;
    const int* lst;
    if (g < NR) {
        n_rows = g_count[g];
        Wu = w_up + (size_t)g * DIMX * HIDX;
        Wg = w_gate + (size_t)g * DIMX * HIDX;
        H = g_hr;
        base = g_offset[g];
        lst = g_list + g * TT;
    } else {
        n_rows = TT; Wu = ws_up; Wg = ws_gate; H = g_hs; base = 0; lst = nullptr;
    }
    const int m0 = blockIdx.y * BM;
    if (m0 >= n_rows) return;
    const int n0 = blockIdx.x * BN_UG;

    __shared__ float As[2][BM][BKK + 4];
    __shared__ float BuS[2][BKK][BN_UG + 4];
    __shared__ float BgS[2][BKK][BN_UG + 4];

    const int tid = threadIdx.x;
    const int lane = tid & 31;
    const int warp = tid >> 5;
    const int wm = warp >> 2;  // 0..1
    const int wn = warp & 3;   // 0..3
    const int gid = lane >> 2;
    const int qp = lane & 3;

    // A loader mapping: 64 rows per pass, 2 passes; 4 float4 per row
    const int ra = tid >> 2;
    const int ca = (tid & 3) * 4;
    const float* aptr[2];
#pragma unroll
    for (int rr = 0; rr < 2; ++rr) {
        int m = m0 + ra + rr * 64;
        int mm = m < n_rows ? m : n_rows - 1;
        int tok = (g < NR) ? lst[mm] : mm;
        aptr[rr] = x + (size_t)tok * DIMX + ca;
    }
    // B loader: 16 rows, 16 float4 per row
    const int rb = tid >> 4;
    const int cb = (tid & 15) * 4;
    const float* buptr = Wu + (size_t)rb * HIDX + n0 + cb;
    const float* bgptr = Wg + (size_t)rb * HIDX + n0 + cb;

    float accU[4][2][4], accG[4][2][4];
#pragma unroll
    for (int i = 0; i < 4; ++i)
#pragma unroll
        for (int j = 0; j < 2; ++j)
#pragma unroll
            for (int k = 0; k < 4; ++k) { accU[i][j][k] = 0.f; accG[i][j][k] = 0.f; }

    float4 pa0, pa1, pu, pg;
    // prefetch k0 = 0
    pa0 = *(const float4*)(aptr[0]);
    pa1 = *(const float4*)(aptr[1]);
    pu = *(const float4*)(buptr);
    pg = *(const float4*)(bgptr);
    {
        As[0][ra][ca + 0] = to_tf32(pa0.x); As[0][ra][ca + 1] = to_tf32(pa0.y);
        As[0][ra][ca + 2] = to_tf32(pa0.z); As[0][ra][ca + 3] = to_tf32(pa0.w);
        As[0][ra + 64][ca + 0] = to_tf32(pa1.x); As[0][ra + 64][ca + 1] = to_tf32(pa1.y);
        As[0][ra + 64][ca + 2] = to_tf32(pa1.z); As[0][ra + 64][ca + 3] = to_tf32(pa1.w);
        BuS[0][rb][cb + 0] = to_tf32(pu.x); BuS[0][rb][cb + 1] = to_tf32(pu.y);
        BuS[0][rb][cb + 2] = to_tf32(pu.z); BuS[0][rb][cb + 3] = to_tf32(pu.w);
        BgS[0][rb][cb + 0] = to_tf32(pg.x); BgS[0][rb][cb + 1] = to_tf32(pg.y);
        BgS[0][rb][cb + 2] = to_tf32(pg.z); BgS[0][rb][cb + 3] = to_tf32(pg.w);
    }
    __syncthreads();

    const int KT = DIMX / BKK;  // 64
    for (int kt = 0; kt < KT; ++kt) {
        const int s = kt & 1;
        if (kt + 1 < KT) {
            const int k0 = (kt + 1) * BKK;
            pa0 = *(const float4*)(aptr[0] + k0);
            pa1 = *(const float4*)(aptr[1] + k0);
            pu = *(const float4*)(buptr + (size_t)k0 * HIDX);
            pg = *(const float4*)(bgptr + (size_t)k0 * HIDX);
        }
        // compute on stage s
#pragma unroll
        for (int ks = 0; ks < BKK / 8; ++ks) {
            uint32_t a[4][4], bu[2][2], bg[2][2];
#pragma unroll
            for (int mf = 0; mf < 4; ++mf) {
                const int r = wm * 64 + mf * 16 + gid;
                const int k = ks * 8 + qp;
                a[mf][0] = __float_as_uint(As[s][r][k]);
                a[mf][1] = __float_as_uint(As[s][r + 8][k]);
                a[mf][2] = __float_as_uint(As[s][r][k + 4]);
                a[mf][3] = __float_as_uint(As[s][r + 8][k + 4]);
            }
#pragma unroll
            for (int nf = 0; nf < 2; ++nf) {
                const int c = wn * 16 + nf * 8 + gid;
                bu[nf][0] = __float_as_uint(BuS[s][ks * 8 + qp][c]);
                bu[nf][1] = __float_as_uint(BuS[s][ks * 8 + qp + 4][c]);
                bg[nf][0] = __float_as_uint(BgS[s][ks * 8 + qp][c]);
                bg[nf][1] = __float_as_uint(BgS[s][ks * 8 + qp + 4][c]);
            }
#pragma unroll
            for (int mf = 0; mf < 4; ++mf)
#pragma unroll
                for (int nf = 0; nf < 2; ++nf) {
                    mma_tf32(accU[mf][nf], a[mf], bu[nf]);
                    mma_tf32(accG[mf][nf], a[mf], bg[nf]);
                }
        }
        if (kt + 1 < KT) {
            const int d = s ^ 1;
            As[d][ra][ca + 0] = to_tf32(pa0.x); As[d][ra][ca + 1] = to_tf32(pa0.y);
            As[d][ra][ca + 2] = to_tf32(pa0.z); As[d][ra][ca + 3] = to_tf32(pa0.w);
            As[d][ra + 64][ca + 0] = to_tf32(pa1.x); As[d][ra + 64][ca + 1] = to_tf32(pa1.y);
            As[d][ra + 64][ca + 2] = to_tf32(pa1.z); As[d][ra + 64][ca + 3] = to_tf32(pa1.w);
            BuS[d][rb][cb + 0] = to_tf32(pu.x); BuS[d][rb][cb + 1] = to_tf32(pu.y);
            BuS[d][rb][cb + 2] = to_tf32(pu.z); BuS[d][rb][cb + 3] = to_tf32(pu.w);
            BgS[d][rb][cb + 0] = to_tf32(pg.x); BgS[d][rb][cb + 1] = to_tf32(pg.y);
            BgS[d][rb][cb + 2] = to_tf32(pg.z); BgS[d][rb][cb + 3] = to_tf32(pg.w);
            __syncthreads();
        }
    }

    // epilogue: h = up * silu(gate), fp32 scratch
#pragma unroll
    for (int mf = 0; mf < 4; ++mf)
#pragma unroll
        for (int nf = 0; nf < 2; ++nf) {
            const int cloc = n0 + wn * 16 + nf * 8 + qp * 2;
#pragma unroll
            for (int half = 0; half < 2; ++half) {
                const int r = wm * 64 + mf * 16 + gid + half * 8;
                const int m = m0 + r;
                if (m < n_rows) {
                    float u0 = accU[mf][nf][half * 2 + 0];
                    float u1 = accU[mf][nf][half * 2 + 1];
                    float gv0 = accG[mf][nf][half * 2 + 0];
                    float gv1 = accG[mf][nf][half * 2 + 1];
                    float h0 = u0 * (gv0 / (1.f + expf(-gv0)));
                    float h1 = u1 * (gv1 / (1.f + expf(-gv1)));
                    *(float2*)(H + (size_t)(base + m) * HIDX + cloc) = make_float2(h0, h1);
                }
            }
        }
}

// -------- down GEMM: shared_mode writes, routed accumulates --------
__global__ __launch_bounds__(256, 2) void down_kernel(
    const float* __restrict__ w_down, float* __restrict__ out, int shared_mode) {
    int n_rows, base;
    const float* Wd;
    const float* Hsrc;
    const int* lst;
    if (shared_mode) {
        n_rows = TT; Wd = w_down; Hsrc = g_hs; base = 0; lst = nullptr;
    } else {
        const int g = blockIdx.z;
        n_rows = g_count[g];
        Wd = w_down + (size_t)g * HIDX * DIMX;
        Hsrc = g_hr;
        base = g_offset[g];
        lst = g_list + g * TT;
    }
    const int m0 = blockIdx.y * BM;
    if (m0 >= n_rows) return;
    const int n0 = blockIdx.x * BN_D;

    __shared__ float As[2][BM][BKK + 4];
    __shared__ float Bs[2][BKK][BN_D + 4];

    const int tid = threadIdx.x;
    const int lane = tid & 31;
    const int warp = tid >> 5;
    const int wm = warp >> 2;
    const int wn = warp & 3;
    const int gid = lane >> 2;
    const int qp = lane & 3;

    const int ra = tid >> 2;
    const int ca = (tid & 3) * 4;
    const float* aptr[2];
#pragma unroll
    for (int rr = 0; rr < 2; ++rr) {
        int m = m0 + ra + rr * 64;
        int mm = m < n_rows ? m : n_rows - 1;
        aptr[rr] = Hsrc + (size_t)(base + mm) * HIDX + ca;
    }
    const int rb = tid >> 5;          // 0..7
    const int cb = (tid & 31) * 4;    // 0..124
    const float* bptr0 = Wd + (size_t)rb * DIMX + n0 + cb;
    const float* bptr1 = Wd + (size_t)(rb + 8) * DIMX + n0 + cb;

    float acc[4][4][4];
#pragma unroll
    for (int i = 0; i < 4; ++i)
#pragma unroll
        for (int j = 0; j < 4; ++j)
#pragma unroll
            for (int k = 0; k < 4; ++k) acc[i][j][k] = 0.f;

    float4 pa0, pa1, pb0, pb1;
    pa0 = *(const float4*)(aptr[0]);
    pa1 = *(const float4*)(aptr[1]);
    pb0 = *(const float4*)(bptr0);
    pb1 = *(const float4*)(bptr1);
    {
        As[0][ra][ca + 0] = to_tf32(pa0.x); As[0][ra][ca + 1] = to_tf32(pa0.y);
        As[0][ra][ca + 2] = to_tf32(pa0.z); As[0][ra][ca + 3] = to_tf32(pa0.w);
        As[0][ra + 64][ca + 0] = to_tf32(pa1.x); As[0][ra + 64][ca + 1] = to_tf32(pa1.y);
        As[0][ra + 64][ca + 2] = to_tf32(pa1.z); As[0][ra + 64][ca + 3] = to_tf32(pa1.w);
        Bs[0][rb][cb + 0] = to_tf32(pb0.x); Bs[0][rb][cb + 1] = to_tf32(pb0.y);
        Bs[0][rb][cb + 2] = to_tf32(pb0.z); Bs[0][rb][cb + 3] = to_tf32(pb0.w);
        Bs[0][rb + 8][cb + 0] = to_tf32(pb1.x); Bs[0][rb + 8][cb + 1] = to_tf32(pb1.y);
        Bs[0][rb + 8][cb + 2] = to_tf32(pb1.z); Bs[0][rb + 8][cb + 3] = to_tf32(pb1.w);
    }
    __syncthreads();

    const int KT = HIDX / BKK;  // 256
    for (int kt = 0; kt < KT; ++kt) {
        const int s = kt & 1;
        if (kt + 1 < KT) {
            const int k0 = (kt + 1) * BKK;
            pa0 = *(const float4*)(aptr[0] + k0);
            pa1 = *(const float4*)(aptr[1] + k0);
            pb0 = *(const float4*)(bptr0 + (size_t)k0 * DIMX);
            pb1 = *(const float4*)(bptr1 + (size_t)k0 * DIMX);
        }
#pragma unroll
        for (int ks = 0; ks < BKK / 8; ++ks) {
            uint32_t a[4][4], b[4][2];
#pragma unroll
            for (int mf = 0; mf < 4; ++mf) {
                const int r = wm * 64 + mf * 16 + gid;
                const int k = ks * 8 + qp;
                a[mf][0] = __float_as_uint(As[s][r][k]);
                a[mf][1] = __float_as_uint(As[s][r + 8][k]);
                a[mf][2] = __float_as_uint(As[s][r][k + 4]);
                a[mf][3] = __float_as_uint(As[s][r + 8][k + 4]);
            }
#pragma unroll
            for (int nf = 0; nf < 4; ++nf) {
                const int c = wn * 32 + nf * 8 + gid;
                b[nf][0] = __float_as_uint(Bs[s][ks * 8 + qp][c]);
                b[nf][1] = __float_as_uint(Bs[s][ks * 8 + qp + 4][c]);
            }
#pragma unroll
            for (int mf = 0; mf < 4; ++mf)
#pragma unroll
                for (int nf = 0; nf < 4; ++nf) mma_tf32(acc[mf][nf], a[mf], b[nf]);
        }
        if (kt + 1 < KT) {
            const int d = s ^ 1;
            As[d][ra][ca + 0] = to_tf32(pa0.x); As[d][ra][ca + 1] = to_tf32(pa0.y);
            As[d][ra][ca + 2] = to_tf32(pa0.z); As[d][ra][ca + 3] = to_tf32(pa0.w);
            As[d][ra + 64][ca + 0] = to_tf32(pa1.x); As[d][ra + 64][ca + 1] = to_tf32(pa1.y);
            As[d][ra + 64][ca + 2] = to_tf32(pa1.z); As[d][ra + 64][ca + 3] = to_tf32(pa1.w);
            Bs[d][rb][cb + 0] = to_tf32(pb0.x); Bs[d][rb][cb + 1] = to_tf32(pb0.y);
            Bs[d][rb][cb + 2] = to_tf32(pb0.z); Bs[d][rb][cb + 3] = to_tf32(pb0.w);
            Bs[d][rb + 8][cb + 0] = to_tf32(pb1.x); Bs[d][rb + 8][cb + 1] = to_tf32(pb1.y);
            Bs[d][rb + 8][cb + 2] = to_tf32(pb1.z); Bs[d][rb + 8][cb + 3] = to_tf32(pb1.w);
            __syncthreads();
        }
    }

#pragma unroll
    for (int mf = 0; mf < 4; ++mf)
#pragma unroll
        for (int nf = 0; nf < 4; ++nf) {
            const int col = n0 + wn * 32 + nf * 8 + qp * 2;
#pragma unroll
            for (int half = 0; half < 2; ++half) {
                const int r = wm * 64 + mf * 16 + gid + half * 8;
                const int m = m0 + r;
                if (m < n_rows) {
                    float v0 = acc[mf][nf][half * 2 + 0];
                    float v1 = acc[mf][nf][half * 2 + 1];
                    if (shared_mode) {
                        *(float2*)(out + (size_t)m * DIMX + col) = make_float2(v0, v1);
                    } else {
                        const int tok = lst[m];
                        const float w = g_wtok[tok];
                        float2* p = (float2*)(out + (size_t)tok * DIMX + col);
                        float2 o = *p;
                        o.x += w * v0;
                        o.y += w * v1;
                        *p = o;
                    }
                }
            }
        }
}

extern "C" void kernel_launch(void* const* d_in, const int* in_sizes, int n_in,
                              void* d_out, int out_size) {
    (void)in_sizes; (void)n_in; (void)out_size;
    const float* x = (const float*)d_in[0];
    const float* w_router = (const float*)d_in[1];
    const float* w_up = (const float*)d_in[2];
    const float* w_gate = (const float*)d_in[3];
    const float* w_down = (const float*)d_in[4];
    const float* ws_up = (const float*)d_in[5];
    const float* ws_gate = (const float*)d_in[6];
    const float* ws_down = (const float*)d_in[7];
    float* out = (float*)d_out;

    init_kernel<<<1, 32>>>();
    router_kernel<<<TT / 8, 256>>>(x, w_router);
    offsets_kernel<<<1, 32>>>();
    upgate_kernel<<<dim3(HIDX / BN_UG, TT / BM, NEXP), 256>>>(x, w_up, w_gate, ws_up, ws_gate);
    down_kernel<<<dim3(DIMX / BN_D, TT / BM, 1), 256>>>(ws_down, out, 1);
    down_kernel<<<dim3(DIMX / BN_D, TT / BM, NR), 256>>>(w_down, out, 0);
}

// round 6
// speedup vs baseline: 1.0011x; 1.0011x over previous
#include <cuda_runtime.h>
#include <cstdint>

#define TT 2048
#define DIMX 1024
#define HIDX 4096
#define NEXP 8
#define NR 7
#define ALPHAF 2.0f

#define BM 128
#define BN_UG 64
#define BN_D 128
#define BKK 16

// -------- device scratch (no allocations allowed) --------
__device__ int g_count[NEXP];
__device__ int g_offset[NR];
__device__ int g_list[NR * TT];
__device__ float g_wtok[TT];
__device__ float g_hr[(size_t)TT * HIDX];  // routed h, rows = offset[e]+slot
__device__ float g_hs[(size_t)TT * HIDX];  // shared h, rows = token

__device__ __forceinline__ float to_tf32(float x) {
    float r;
    asm("cvt.rna.tf32.f32 %0, %1;" : "=f"(r) : "f"(x));
    return r;
}

__device__ __forceinline__ void mma_tf32(float* d, const uint32_t* a, const uint32_t* b) {
    asm volatile(
        "mma.sync.aligned.m16n8k8.row.col.f32.tf32.tf32.f32 "
        "{%0,%1,%2,%3}, {%4,%5,%6,%7}, {%8,%9}, {%0,%1,%2,%3};"
        : "+f"(d[0]), "+f"(d[1]), "+f"(d[2]), "+f"(d[3])
        : "r"(a[0]), "r"(a[1]), "r"(a[2]), "r"(a[3]), "r"(b[0]), "r"(b[1]));
}

// -------- init: zero group counts --------
__global__ void init_kernel() {
    if (threadIdx.x < NEXP) g_count[threadIdx.x] = 0;
}

// -------- router: fp32 logits, softmax, top-1, build lists --------
__global__ void router_kernel(const float* __restrict__ x, const float* __restrict__ wr) {
    __shared__ float sw[DIMX * NEXP];  // 32KB
    for (int i = threadIdx.x; i < DIMX * NEXP; i += blockDim.x) sw[i] = wr[i];
    __syncthreads();
    const int warp = threadIdx.x >> 5;
    const int lane = threadIdx.x & 31;
    const int tok = blockIdx.x * 8 + warp;
    if (tok >= TT) return;
    const float* xr = x + (size_t)tok * DIMX;
    float acc[NEXP];
#pragma unroll
    for (int e = 0; e < NEXP; ++e) acc[e] = 0.f;
    for (int k = lane; k < DIMX; k += 32) {
        float xv = xr[k];
#pragma unroll
        for (int e = 0; e < NEXP; ++e) acc[e] += xv * sw[k * NEXP + e];
    }
#pragma unroll
    for (int e = 0; e < NEXP; ++e)
#pragma unroll
        for (int o = 16; o; o >>= 1) acc[e] += __shfl_xor_sync(~0u, acc[e], o);
    if (lane == 0) {
        float m = acc[0];
        int idx = 0;
#pragma unroll
        for (int e = 1; e < NEXP; ++e)
            if (acc[e] > m) { m = acc[e]; idx = e; }
        float s = 0.f;
#pragma unroll
        for (int e = 0; e < NEXP; ++e) s += expf(acc[e] - m);
        float p = 1.0f / s;  // prob of argmax
        g_wtok[tok] = ALPHAF * p;
        if (idx < NR) {
            int slot = atomicAdd(&g_count[idx], 1);
            g_list[idx * TT + slot] = tok;
        }
    }
}

// -------- tiny exclusive prefix over counts --------
__global__ void offsets_kernel() {
    if (threadIdx.x == 0) {
        int off = 0;
        for (int e = 0; e < NR; ++e) { g_offset[e] = off; off += g_count[e]; }
    }
}

// -------- grouped up+gate GEMM with fused SwiGLU epilogue --------
__global__ __launch_bounds__(256, 2) void upgate_kernel(
    const float* __restrict__ x,
    const float* __restrict__ w_up, const float* __restrict__ w_gate,
    const float* __restrict__ ws_up, const float* __restrict__ ws_gate) {
    const int g = blockIdx.z;
    int n_rows, base;
    const float *Wu, *Wg;
    float* H;
    const int* lst;
    if (g < NR) {
        n_rows = g_count[g];
        Wu = w_up + (size_t)g * DIMX * HIDX;
        Wg = w_gate + (size_t)g * DIMX * HIDX;
        H = g_hr;
        base = g_offset[g];
        lst = g_list + g * TT;
    } else {
        n_rows = TT; Wu = ws_up; Wg = ws_gate; H = g_hs; base = 0; lst = nullptr;
    }
    const int m0 = blockIdx.y * BM;
    if (m0 >= n_rows) return;
    const int n0 = blockIdx.x * BN_UG;

    __shared__ float As[2][BM][BKK + 4];
    __shared__ float BuS[2][BKK][BN_UG + 4];
    __shared__ float BgS[2][BKK][BN_UG + 4];

    const int tid = threadIdx.x;
    const int lane = tid & 31;
    const int warp = tid >> 5;
    const int wm = warp >> 2;  // 0..1
    const int wn = warp & 3;   // 0..3
    const int gid = lane >> 2;
    const int qp = lane & 3;

    // A loader mapping: 64 rows per pass, 2 passes; 4 float4 per row
    const int ra = tid >> 2;
    const int ca = (tid & 3) * 4;
    const float* aptr[2];
#pragma unroll
    for (int rr = 0; rr < 2; ++rr) {
        int m = m0 + ra + rr * 64;
        int mm = m < n_rows ? m : n_rows - 1;
        int tok = (g < NR) ? lst[mm] : mm;
        aptr[rr] = x + (size_t)tok * DIMX + ca;
    }
    // B loader: 16 rows, 16 float4 per row
    const int rb = tid >> 4;
    const int cb = (tid & 15) * 4;
    const float* buptr = Wu + (size_t)rb * HIDX + n0 + cb;
    const float* bgptr = Wg + (size_t)rb * HIDX + n0 + cb;

    float accU[4][2][4], accG[4][2][4];
#pragma unroll
    for (int i = 0; i < 4; ++i)
#pragma unroll
        for (int j = 0; j < 2; ++j)
#pragma unroll
            for (int k = 0; k < 4; ++k) { accU[i][j][k] = 0.f; accG[i][j][k] = 0.f; }

    float4 pa0, pa1, pu, pg;
    // prefetch k0 = 0
    pa0 = *(const float4*)(aptr[0]);
    pa1 = *(const float4*)(aptr[1]);
    pu = *(const float4*)(buptr);
    pg = *(const float4*)(bgptr);
    {
        As[0][ra][ca + 0] = to_tf32(pa0.x); As[0][ra][ca + 1] = to_tf32(pa0.y);
        As[0][ra][ca + 2] = to_tf32(pa0.z); As[0][ra][ca + 3] = to_tf32(pa0.w);
        As[0][ra + 64][ca + 0] = to_tf32(pa1.x); As[0][ra + 64][ca + 1] = to_tf32(pa1.y);
        As[0][ra + 64][ca + 2] = to_tf32(pa1.z); As[0][ra + 64][ca + 3] = to_tf32(pa1.w);
        BuS[0][rb][cb + 0] = to_tf32(pu.x); BuS[0][rb][cb + 1] = to_tf32(pu.y);
        BuS[0][rb][cb + 2] = to_tf32(pu.z); BuS[0][rb][cb + 3] = to_tf32(pu.w);
        BgS[0][rb][cb + 0] = to_tf32(pg.x); BgS[0][rb][cb + 1] = to_tf32(pg.y);
        BgS[0][rb][cb + 2] = to_tf32(pg.z); BgS[0][rb][cb + 3] = to_tf32(pg.w);
    }
    __syncthreads();

    const int KT = DIMX / BKK;  // 64
    for (int kt = 0; kt < KT; ++kt) {
        const int s = kt & 1;
        if (kt + 1 < KT) {
            const int k0 = (kt + 1) * BKK;
            pa0 = *(const float4*)(aptr[0] + k0);
            pa1 = *(const float4*)(aptr[1] + k0);
            pu = *(const float4*)(buptr + (size_t)k0 * HIDX);
            pg = *(const float4*)(bgptr + (size_t)k0 * HIDX);
        }
        // compute on stage s
#pragma unroll
        for (int ks = 0; ks < BKK / 8; ++ks) {
            uint32_t a[4][4], bu[2][2], bg[2][2];
#pragma unroll
            for (int mf = 0; mf < 4; ++mf) {
                const int r = wm * 64 + mf * 16 + gid;
                const int k = ks * 8 + qp;
                a[mf][0] = __float_as_uint(As[s][r][k]);
                a[mf][1] = __float_as_uint(As[s][r + 8][k]);
                a[mf][2] = __float_as_uint(As[s][r][k + 4]);
                a[mf][3] = __float_as_uint(As[s][r + 8][k + 4]);
            }
#pragma unroll
            for (int nf = 0; nf < 2; ++nf) {
                const int c = wn * 16 + nf * 8 + gid;
                bu[nf][0] = __float_as_uint(BuS[s][ks * 8 + qp][c]);
                bu[nf][1] = __float_as_uint(BuS[s][ks * 8 + qp + 4][c]);
                bg[nf][0] = __float_as_uint(BgS[s][ks * 8 + qp][c]);
                bg[nf][1] = __float_as_uint(BgS[s][ks * 8 + qp + 4][c]);
            }
#pragma unroll
            for (int mf = 0; mf < 4; ++mf)
#pragma unroll
                for (int nf = 0; nf < 2; ++nf) {
                    mma_tf32(accU[mf][nf], a[mf], bu[nf]);
                    mma_tf32(accG[mf][nf], a[mf], bg[nf]);
                }
        }
        if (kt + 1 < KT) {
            const int d = s ^ 1;
            As[d][ra][ca + 0] = to_tf32(pa0.x); As[d][ra][ca + 1] = to_tf32(pa0.y);
            As[d][ra][ca + 2] = to_tf32(pa0.z); As[d][ra][ca + 3] = to_tf32(pa0.w);
            As[d][ra + 64][ca + 0] = to_tf32(pa1.x); As[d][ra + 64][ca + 1] = to_tf32(pa1.y);
            As[d][ra + 64][ca + 2] = to_tf32(pa1.z); As[d][ra + 64][ca + 3] = to_tf32(pa1.w);
            BuS[d][rb][cb + 0] = to_tf32(pu.x); BuS[d][rb][cb + 1] = to_tf32(pu.y);
            BuS[d][rb][cb + 2] = to_tf32(pu.z); BuS[d][rb][cb + 3] = to_tf32(pu.w);
            BgS[d][rb][cb + 0] = to_tf32(pg.x); BgS[d][rb][cb + 1] = to_tf32(pg.y);
            BgS[d][rb][cb + 2] = to_tf32(pg.z); BgS[d][rb][cb + 3] = to_tf32(pg.w);
            __syncthreads();
        }
    }

    // epilogue: h = up * silu(gate), fp32 scratch
#pragma unroll
    for (int mf = 0; mf < 4; ++mf)
#pragma unroll
        for (int nf = 0; nf < 2; ++nf) {
            const int cloc = n0 + wn * 16 + nf * 8 + qp * 2;
#pragma unroll
            for (int half = 0; half < 2; ++half) {
                const int r = wm * 64 + mf * 16 + gid + half * 8;
                const int m = m0 + r;
                if (m < n_rows) {
                    float u0 = accU[mf][nf][half * 2 + 0];
                    float u1 = accU[mf][nf][half * 2 + 1];
                    float gv0 = accG[mf][nf][half * 2 + 0];
                    float gv1 = accG[mf][nf][half * 2 + 1];
                    float h0 = u0 * (gv0 / (1.f + expf(-gv0)));
                    float h1 = u1 * (gv1 / (1.f + expf(-gv1)));
                    *(float2*)(H + (size_t)(base + m) * HIDX + cloc) = make_float2(h0, h1);
                }
            }
        }
}

// -------- down GEMM: shared_mode writes, routed accumulates --------
__global__ __launch_bounds__(256, 2) void down_kernel(
    const float* __restrict__ w_down, float* __restrict__ out, int shared_mode) {
    int n_rows, base;
    const float* Wd;
    const float* Hsrc;
    const int* lst;
    if (shared_mode) {
        n_rows = TT; Wd = w_down; Hsrc = g_hs; base = 0; lst = nullptr;
    } else {
        const int g = blockIdx.z;
        n_rows = g_count[g];
        Wd = w_down + (size_t)g * HIDX * DIMX;
        Hsrc = g_hr;
        base = g_offset[g];
        lst = g_list + g * TT;
    }
    const int m0 = blockIdx.y * BM;
    if (m0 >= n_rows) return;
    const int n0 = blockIdx.x * BN_D;

    __shared__ float As[2][BM][BKK + 4];
    __shared__ float Bs[2][BKK][BN_D + 4];

    const int tid = threadIdx.x;
    const int lane = tid & 31;
    const int warp = tid >> 5;
    const int wm = warp >> 2;
    const int wn = warp & 3;
    const int gid = lane >> 2;
    const int qp = lane & 3;

    const int ra = tid >> 2;
    const int ca = (tid & 3) * 4;
    const float* aptr[2];
#pragma unroll
    for (int rr = 0; rr < 2; ++rr) {
        int m = m0 + ra + rr * 64;
        int mm = m < n_rows ? m : n_rows - 1;
        aptr[rr] = Hsrc + (size_t)(base + mm) * HIDX + ca;
    }
    const int rb = tid >> 5;          // 0..7
    const int cb = (tid & 31) * 4;    // 0..124
    const float* bptr0 = Wd + (size_t)rb * DIMX + n0 + cb;
    const float* bptr1 = Wd + (size_t)(rb + 8) * DIMX + n0 + cb;

    float acc[4][4][4];
#pragma unroll
    for (int i = 0; i < 4; ++i)
#pragma unroll
        for (int j = 0; j < 4; ++j)
#pragma unroll
            for (int k = 0; k < 4; ++k) acc[i][j][k] = 0.f;

    float4 pa0, pa1, pb0, pb1;
    pa0 = *(const float4*)(aptr[0]);
    pa1 = *(const float4*)(aptr[1]);
    pb0 = *(const float4*)(bptr0);
    pb1 = *(const float4*)(bptr1);
    {
        As[0][ra][ca + 0] = to_tf32(pa0.x); As[0][ra][ca + 1] = to_tf32(pa0.y);
        As[0][ra][ca + 2] = to_tf32(pa0.z); As[0][ra][ca + 3] = to_tf32(pa0.w);
        As[0][ra + 64][ca + 0] = to_tf32(pa1.x); As[0][ra + 64][ca + 1] = to_tf32(pa1.y);
        As[0][ra + 64][ca + 2] = to_tf32(pa1.z); As[0][ra + 64][ca + 3] = to_tf32(pa1.w);
        Bs[0][rb][cb + 0] = to_tf32(pb0.x); Bs[0][rb][cb + 1] = to_tf32(pb0.y);
        Bs[0][rb][cb + 2] = to_tf32(pb0.z); Bs[0][rb][cb + 3] = to_tf32(pb0.w);
        Bs[0][rb + 8][cb + 0] = to_tf32(pb1.x); Bs[0][rb + 8][cb + 1] = to_tf32(pb1.y);
        Bs[0][rb + 8][cb + 2] = to_tf32(pb1.z); Bs[0][rb + 8][cb + 3] = to_tf32(pb1.w);
    }
    __syncthreads();

    const int KT = HIDX / BKK;  // 256
    for (int kt = 0; kt < KT; ++kt) {
        const int s = kt & 1;
        if (kt + 1 < KT) {
            const int k0 = (kt + 1) * BKK;
            pa0 = *(const float4*)(aptr[0] + k0);
            pa1 = *(const float4*)(aptr[1] + k0);
            pb0 = *(const float4*)(bptr0 + (size_t)k0 * DIMX);
            pb1 = *(const float4*)(bptr1 + (size_t)k0 * DIMX);
        }
#pragma unroll
        for (int ks = 0; ks < BKK / 8; ++ks) {
            uint32_t a[4][4], b[4][2];
#pragma unroll
            for (int mf = 0; mf < 4; ++mf) {
                const int r = wm * 64 + mf * 16 + gid;
                const int k = ks * 8 + qp;
                a[mf][0] = __float_as_uint(As[s][r][k]);
                a[mf][1] = __float_as_uint(As[s][r + 8][k]);
                a[mf][2] = __float_as_uint(As[s][r][k + 4]);
                a[mf][3] = __float_as_uint(As[s][r + 8][k + 4]);
            }
#pragma unroll
            for (int nf = 0; nf < 4; ++nf) {
                const int c = wn * 32 + nf * 8 + gid;
                b[nf][0] = __float_as_uint(Bs[s][ks * 8 + qp][c]);
                b[nf][1] = __float_as_uint(Bs[s][ks * 8 + qp + 4][c]);
            }
#pragma unroll
            for (int mf = 0; mf < 4; ++mf)
#pragma unroll
                for (int nf = 0; nf < 4; ++nf) mma_tf32(acc[mf][nf], a[mf], b[nf]);
        }
        if (kt + 1 < KT) {
            const int d = s ^ 1;
            As[d][ra][ca + 0] = to_tf32(pa0.x); As[d][ra][ca + 1] = to_tf32(pa0.y);
            As[d][ra][ca + 2] = to_tf32(pa0.z); As[d][ra][ca + 3] = to_tf32(pa0.w);
            As[d][ra + 64][ca + 0] = to_tf32(pa1.x); As[d][ra + 64][ca + 1] = to_tf32(pa1.y);
            As[d][ra + 64][ca + 2] = to_tf32(pa1.z); As[d][ra + 64][ca + 3] = to_tf32(pa1.w);
            Bs[d][rb][cb + 0] = to_tf32(pb0.x); Bs[d][rb][cb + 1] = to_tf32(pb0.y);
            Bs[d][rb][cb + 2] = to_tf32(pb0.z); Bs[d][rb][cb + 3] = to_tf32(pb0.w);
            Bs[d][rb + 8][cb + 0] = to_tf32(pb1.x); Bs[d][rb + 8][cb + 1] = to_tf32(pb1.y);
            Bs[d][rb + 8][cb + 2] = to_tf32(pb1.z); Bs[d][rb + 8][cb + 3] = to_tf32(pb1.w);
            __syncthreads();
        }
    }

#pragma unroll
    for (int mf = 0; mf < 4; ++mf)
#pragma unroll
        for (int nf = 0; nf < 4; ++nf) {
            const int col = n0 + wn * 32 + nf * 8 + qp * 2;
#pragma unroll
            for (int half = 0; half < 2; ++half) {
                const int r = wm * 64 + mf * 16 + gid + half * 8;
                const int m = m0 + r;
                if (m < n_rows) {
                    float v0 = acc[mf][nf][half * 2 + 0];
                    float v1 = acc[mf][nf][half * 2 + 1];
                    if (shared_mode) {
                        *(float2*)(out + (size_t)m * DIMX + col) = make_float2(v0, v1);
                    } else {
                        const int tok = lst[m];
                        const float w = g_wtok[tok];
                        float2* p = (float2*)(out + (size_t)tok * DIMX + col);
                        float2 o = *p;
                        o.x += w * v0;
                        o.y += w * v1;
                        *p = o;
                    }
                }
            }
        }
}

extern "C" void kernel_launch(void* const* d_in, const int* in_sizes, int n_in,
                              void* d_out, int out_size) {
    (void)in_sizes; (void)n_in; (void)out_size;
    const float* x = (const float*)d_in[0];
    const float* w_router = (const float*)d_in[1];
    const float* w_up = (const float*)d_in[2];
    const float* w_gate = (const float*)d_in[3];
    const float* w_down = (const float*)d_in[4];
    const float* ws_up = (const float*)d_in[5];
    const float* ws_gate = (const float*)d_in[6];
    const float* ws_down = (const float*)d_in[7];
    float* out = (float*)d_out;

    init_kernel<<<1, 32>>>();
    router_kernel<<<TT / 8, 256>>>(x, w_router);
    offsets_kernel<<<1, 32>>>();
    upgate_kernel<<<dim3(HIDX / BN_UG, TT / BM, NEXP), 256>>>(x, w_up, w_gate, ws_up, ws_gate);
    down_kernel<<<dim3(DIMX / BN_D, TT / BM, 1), 256>>>(ws_down, out, 1);
    down_kernel<<<dim3(DIMX / BN_D, TT / BM, NR), 256>>>(w_down, out, 0);
}

// round 11
// speedup vs baseline: 1.1750x; 1.1738x over previous
#include <cuda_runtime.h>
#include <cuda_fp16.h>
#include <cstdint>
#include <cstring>

#define TT 2048
#define DIMX 1024
#define HIDX 4096
#define NEXP 8
#define NR 7
#define ALPHAF 2.0f

// ---------------- device scratch ----------------
__device__ int g_count[NEXP];
__device__ int g_offset[NR];
__device__ int g_list[NR * TT];
__device__ float g_wtok[TT];
__device__ __half g_hr[(size_t)TT * HIDX];  // routed h (fp16), compact rows
__device__ __half g_hs[(size_t)TT * HIDX];  // shared h (fp16), row = token

// ---------------- helpers ----------------
__device__ __forceinline__ uint32_t smem_u32(const void* p) {
    uint32_t a;
    asm("{ .reg .u64 t; cvta.to.shared.u64 t, %1; cvt.u32.u64 %0, t; }" : "=r"(a) : "l"(p));
    return a;
}
__device__ __forceinline__ void ldsm_x4(uint32_t* r, uint32_t addr) {
    asm volatile("ldmatrix.sync.aligned.m8n8.x4.shared.b16 {%0,%1,%2,%3}, [%4];"
                 : "=r"(r[0]), "=r"(r[1]), "=r"(r[2]), "=r"(r[3]) : "r"(addr));
}
__device__ __forceinline__ void ldsm_x2t(uint32_t* r, uint32_t addr) {
    asm volatile("ldmatrix.sync.aligned.m8n8.x2.trans.shared.b16 {%0,%1}, [%2];"
                 : "=r"(r[0]), "=r"(r[1]) : "r"(addr));
}
__device__ __forceinline__ void mma_f16(float* d, const uint32_t* a, const uint32_t* b) {
    asm volatile(
        "mma.sync.aligned.m16n8k16.row.col.f32.f16.f16.f32 "
        "{%0,%1,%2,%3}, {%4,%5,%6,%7}, {%8,%9}, {%0,%1,%2,%3};"
        : "+f"(d[0]), "+f"(d[1]), "+f"(d[2]), "+f"(d[3])
        : "r"(a[0]), "r"(a[1]), "r"(a[2]), "r"(a[3]), "r"(b[0]), "r"(b[1]));
}
__device__ __forceinline__ uint32_t h2_bits(__half2 h) {
    uint32_t u;
    memcpy(&u, &h, 4);
    return u;
}
__device__ __forceinline__ uint4 pack8h(float4 lo, float4 hi) {
    uint4 u;
    u.x = h2_bits(__floats2half2_rn(lo.x, lo.y));
    u.y = h2_bits(__floats2half2_rn(lo.z, lo.w));
    u.z = h2_bits(__floats2half2_rn(hi.x, hi.y));
    u.w = h2_bits(__floats2half2_rn(hi.z, hi.w));
    return u;
}

// ---------------- small kernels ----------------
__global__ void init_kernel() {
    if (threadIdx.x < NEXP) g_count[threadIdx.x] = 0;
}

__global__ void router_kernel(const float* __restrict__ x, const float* __restrict__ wr) {
    __shared__ float sw[DIMX * NEXP];
    for (int i = threadIdx.x; i < DIMX * NEXP; i += blockDim.x) sw[i] = wr[i];
    __syncthreads();
    const int warp = threadIdx.x >> 5;
    const int lane = threadIdx.x & 31;
    const int tok = blockIdx.x * 8 + warp;
    if (tok >= TT) return;
    const float* xr = x + (size_t)tok * DIMX;
    float acc[NEXP];
#pragma unroll
    for (int e = 0; e < NEXP; ++e) acc[e] = 0.f;
    for (int k = lane; k < DIMX; k += 32) {
        float xv = xr[k];
#pragma unroll
        for (int e = 0; e < NEXP; ++e) acc[e] += xv * sw[k * NEXP + e];
    }
#pragma unroll
    for (int e = 0; e < NEXP; ++e)
#pragma unroll
        for (int o = 16; o; o >>= 1) acc[e] += __shfl_xor_sync(~0u, acc[e], o);
    if (lane == 0) {
        float m = acc[0];
        int idx = 0;
#pragma unroll
        for (int e = 1; e < NEXP; ++e)
            if (acc[e] > m) { m = acc[e]; idx = e; }
        float s = 0.f;
#pragma unroll
        for (int e = 0; e < NEXP; ++e) s += expf(acc[e] - m);
        g_wtok[tok] = ALPHAF / s;
        if (idx < NR) {
            int slot = atomicAdd(&g_count[idx], 1);
            g_list[idx * TT + slot] = tok;
        }
    }
}

__global__ void offsets_kernel() {
    if (threadIdx.x == 0) {
        int off = 0;
        for (int e = 0; e < NR; ++e) { g_offset[e] = off; off += g_count[e]; }
    }
}

// ---------------- upgate: fp16 mma, fused SwiGLU ----------------
// block 128 thr (4 warps 2m x 2n), tile M=128, N=64 (U and G), BK=16
#define UPG_AS 24   // 16 + 8 pad halves
#define UPG_BS 72   // 64 + 8 pad halves

__global__ __launch_bounds__(128) void upgate_kernel(
    const float* __restrict__ x,
    const float* __restrict__ w_up, const float* __restrict__ w_gate,
    const float* __restrict__ ws_up, const float* __restrict__ ws_gate) {
    const int g = blockIdx.z;
    int n_rows, base;
    const float *Wu, *Wg;
    __half* H;
    const int* lst;
    if (g < NR) {
        n_rows = g_count[g];
        Wu = w_up + (size_t)g * DIMX * HIDX;
        Wg = w_gate + (size_t)g * DIMX * HIDX;
        H = g_hr; base = g_offset[g]; lst = g_list + g * TT;
    } else {
        n_rows = TT; Wu = ws_up; Wg = ws_gate; H = g_hs; base = 0; lst = nullptr;
    }
    const int m0 = blockIdx.y * 128;
    if (m0 >= n_rows) return;
    const int n0 = blockIdx.x * 64;

    __shared__ __half As[2][128][UPG_AS];
    __shared__ __half BuS[2][16][UPG_BS];
    __shared__ __half BgS[2][16][UPG_BS];

    const int t = threadIdx.x;
    const int warp = t >> 5;
    const int lane = t & 31;
    const int wm = warp >> 1;   // 0..1
    const int wn = warp & 1;    // 0..1
    const int gid = lane >> 2;
    const int qp = lane & 3;

    // A loader: thread -> one row
    int mm = m0 + t; if (mm >= n_rows) mm = n_rows - 1;
    const int atok = (g < NR) ? lst[mm] : mm;
    const float* aptr = x + (size_t)atok * DIMX;
    // B loader: k = t>>3 (0..15), n chunk = (t&7)*8
    const int bk = t >> 3, bn = (t & 7) * 8;
    const float* buptr = Wu + (size_t)bk * HIDX + n0 + bn;
    const float* bgptr = Wg + (size_t)bk * HIDX + n0 + bn;

    // ldmatrix lane offsets
    const int lr = (lane & 7) + ((lane >> 3) & 1) * 8;  // row add (A)
    const int lk = (lane >> 4) * 8;                     // k add (A)
    const uint32_t asb = smem_u32(As) + (uint32_t)(((wm * 64 + lr) * UPG_AS + lk) * 2);
    const int bl = lane & 15;
    const uint32_t bub = smem_u32(BuS) + (uint32_t)((bl * UPG_BS + wn * 32) * 2);
    const uint32_t bgb = smem_u32(BgS) + (uint32_t)((bl * UPG_BS + wn * 32) * 2);

    float accU[4][4][4], accG[4][4][4];
#pragma unroll
    for (int i = 0; i < 4; ++i)
#pragma unroll
        for (int j = 0; j < 4; ++j)
#pragma unroll
            for (int k = 0; k < 4; ++k) { accU[i][j][k] = 0.f; accG[i][j][k] = 0.f; }

    float4 pa[4], pu[2], pg[2];
    // prefetch kt=0
#pragma unroll
    for (int j = 0; j < 4; ++j) pa[j] = *(const float4*)(aptr + j * 4);
    pu[0] = *(const float4*)(buptr); pu[1] = *(const float4*)(buptr + 4);
    pg[0] = *(const float4*)(bgptr); pg[1] = *(const float4*)(bgptr + 4);
    {
        *(uint4*)&As[0][t][0] = pack8h(pa[0], pa[1]);
        *(uint4*)&As[0][t][8] = pack8h(pa[2], pa[3]);
        *(uint4*)&BuS[0][bk][bn] = pack8h(pu[0], pu[1]);
        *(uint4*)&BgS[0][bk][bn] = pack8h(pg[0], pg[1]);
    }
    __syncthreads();

    const int KT = DIMX / 16;  // 64
    for (int kt = 0; kt < KT; ++kt) {
        const int s = kt & 1;
        if (kt + 1 < KT) {
            const int k0 = (kt + 1) * 16;
#pragma unroll
            for (int j = 0; j < 4; ++j) pa[j] = *(const float4*)(aptr + k0 + j * 4);
            const size_t bo = (size_t)k0 * HIDX;
            pu[0] = *(const float4*)(buptr + bo); pu[1] = *(const float4*)(buptr + bo + 4);
            pg[0] = *(const float4*)(bgptr + bo); pg[1] = *(const float4*)(bgptr + bo + 4);
        }
        // compute stage s
        uint32_t a[4][4], bu[4][2], bg[4][2];
        const uint32_t sa = asb + (uint32_t)(s * 128 * UPG_AS * 2);
        const uint32_t su = bub + (uint32_t)(s * 16 * UPG_BS * 2);
        const uint32_t sg = bgb + (uint32_t)(s * 16 * UPG_BS * 2);
#pragma unroll
        for (int mf = 0; mf < 4; ++mf) ldsm_x4(a[mf], sa + (uint32_t)(mf * 16 * UPG_AS * 2));
#pragma unroll
        for (int nf = 0; nf < 4; ++nf) {
            ldsm_x2t(bu[nf], su + (uint32_t)(nf * 8 * 2));
            ldsm_x2t(bg[nf], sg + (uint32_t)(nf * 8 * 2));
        }
#pragma unroll
        for (int mf = 0; mf < 4; ++mf)
#pragma unroll
            for (int nf = 0; nf < 4; ++nf) {
                mma_f16(accU[mf][nf], a[mf], bu[nf]);
                mma_f16(accG[mf][nf], a[mf], bg[nf]);
            }
        if (kt + 1 < KT) {
            const int d = s ^ 1;
            *(uint4*)&As[d][t][0] = pack8h(pa[0], pa[1]);
            *(uint4*)&As[d][t][8] = pack8h(pa[2], pa[3]);
            *(uint4*)&BuS[d][bk][bn] = pack8h(pu[0], pu[1]);
            *(uint4*)&BgS[d][bk][bn] = pack8h(pg[0], pg[1]);
            __syncthreads();
        }
    }

    // epilogue: h = up * silu(gate) -> fp16
#pragma unroll
    for (int mf = 0; mf < 4; ++mf)
#pragma unroll
        for (int nf = 0; nf < 4; ++nf) {
            const int col = n0 + wn * 32 + nf * 8 + qp * 2;
#pragma unroll
            for (int half = 0; half < 2; ++half) {
                const int m = m0 + wm * 64 + mf * 16 + gid + half * 8;
                if (m < n_rows) {
                    float u0 = accU[mf][nf][half * 2 + 0];
                    float u1 = accU[mf][nf][half * 2 + 1];
                    float gv0 = accG[mf][nf][half * 2 + 0];
                    float gv1 = accG[mf][nf][half * 2 + 1];
                    float h0 = u0 * (gv0 / (1.f + expf(-gv0)));
                    float h1 = u1 * (gv1 / (1.f + expf(-gv1)));
                    __half2 hv = __floats2half2_rn(h0, h1);
                    *(__half2*)(H + (size_t)(base + m) * HIDX + col) = hv;
                }
            }
        }
}

// ---------------- down: fp16 mma, h @ w_down ----------------
// block 128 thr (4 warps 2m x 2n), tile M=128, N=128, BK=16
#define DWN_AS 24    // 16 + 8
#define DWN_BS 136   // 128 + 8

__global__ __launch_bounds__(128) void down_kernel(
    const float* __restrict__ w_down, float* __restrict__ out, int shared_mode) {
    int n_rows, base;
    const float* Wd;
    const __half* Hsrc;
    const int* lst;
    if (shared_mode) {
        n_rows = TT; Wd = w_down; Hsrc = g_hs; base = 0; lst = nullptr;
    } else {
        const int g = blockIdx.z;
        n_rows = g_count[g];
        Wd = w_down + (size_t)g * HIDX * DIMX;
        Hsrc = g_hr; base = g_offset[g]; lst = g_list + g * TT;
    }
    const int m0 = blockIdx.y * 128;
    if (m0 >= n_rows) return;
    const int n0 = blockIdx.x * 128;

    __shared__ __half As[2][128][DWN_AS];
    __shared__ __half Bs[2][16][DWN_BS];

    const int t = threadIdx.x;
    const int warp = t >> 5;
    const int lane = t & 31;
    const int wm = warp >> 1;
    const int wn = warp & 1;
    const int gid = lane >> 2;
    const int qp = lane & 3;

    int mm = m0 + t; if (mm >= n_rows) mm = n_rows - 1;
    const __half* aptr = Hsrc + (size_t)(base + mm) * HIDX;
    const int bk = t >> 3, bn = (t & 7) * 16;
    const float* bptr = Wd + (size_t)bk * DIMX + n0 + bn;

    const int lr = (lane & 7) + ((lane >> 3) & 1) * 8;
    const int lk = (lane >> 4) * 8;
    const uint32_t asb = smem_u32(As) + (uint32_t)(((wm * 64 + lr) * DWN_AS + lk) * 2);
    const int bl = lane & 15;
    const uint32_t bsb = smem_u32(Bs) + (uint32_t)((bl * DWN_BS + wn * 64) * 2);

    float acc[4][8][4];
#pragma unroll
    for (int i = 0; i < 4; ++i)
#pragma unroll
        for (int j = 0; j < 8; ++j)
#pragma unroll
            for (int k = 0; k < 4; ++k) acc[i][j][k] = 0.f;

    uint4 pa[2];
    float4 pb[4];
    pa[0] = *(const uint4*)(aptr);
    pa[1] = *(const uint4*)(aptr + 8);
#pragma unroll
    for (int j = 0; j < 4; ++j) pb[j] = *(const float4*)(bptr + j * 4);
    {
        *(uint4*)&As[0][t][0] = pa[0];
        *(uint4*)&As[0][t][8] = pa[1];
        *(uint4*)&Bs[0][bk][bn] = pack8h(pb[0], pb[1]);
        *(uint4*)&Bs[0][bk][bn + 8] = pack8h(pb[2], pb[3]);
    }
    __syncthreads();

    const int KT = HIDX / 16;  // 256
    for (int kt = 0; kt < KT; ++kt) {
        const int s = kt & 1;
        if (kt + 1 < KT) {
            const int k0 = (kt + 1) * 16;
            pa[0] = *(const uint4*)(aptr + k0);
            pa[1] = *(const uint4*)(aptr + k0 + 8);
            const size_t bo = (size_t)k0 * DIMX;
#pragma unroll
            for (int j = 0; j < 4; ++j) pb[j] = *(const float4*)(bptr + bo + j * 4);
        }
        uint32_t a[4][4], b[8][2];
        const uint32_t sa = asb + (uint32_t)(s * 128 * DWN_AS * 2);
        const uint32_t sbv = bsb + (uint32_t)(s * 16 * DWN_BS * 2);
#pragma unroll
        for (int mf = 0; mf < 4; ++mf) ldsm_x4(a[mf], sa + (uint32_t)(mf * 16 * DWN_AS * 2));
#pragma unroll
        for (int nf = 0; nf < 8; ++nf) ldsm_x2t(b[nf], sbv + (uint32_t)(nf * 8 * 2));
#pragma unroll
        for (int mf = 0; mf < 4; ++mf)
#pragma unroll
            for (int nf = 0; nf < 8; ++nf) mma_f16(acc[mf][nf], a[mf], b[nf]);
        if (kt + 1 < KT) {
            const int d = s ^ 1;
            *(uint4*)&As[d][t][0] = pa[0];
            *(uint4*)&As[d][t][8] = pa[1];
            *(uint4*)&Bs[d][bk][bn] = pack8h(pb[0], pb[1]);
            *(uint4*)&Bs[d][bk][bn + 8] = pack8h(pb[2], pb[3]);
            __syncthreads();
        }
    }

#pragma unroll
    for (int mf = 0; mf < 4; ++mf)
#pragma unroll
        for (int nf = 0; nf < 8; ++nf) {
            const int col = n0 + wn * 64 + nf * 8 + qp * 2;
#pragma unroll
            for (int half = 0; half < 2; ++half) {
                const int m = m0 + wm * 64 + mf * 16 + gid + half * 8;
                if (m < n_rows) {
                    float v0 = acc[mf][nf][half * 2 + 0];
                    float v1 = acc[mf][nf][half * 2 + 1];
                    if (shared_mode) {
                        *(float2*)(out + (size_t)m * DIMX + col) = make_float2(v0, v1);
                    } else {
                        const int tok = lst[m];
                        const float w = g_wtok[tok];
                        float2* p = (float2*)(out + (size_t)tok * DIMX + col);
                        float2 o = *p;
                        o.x += w * v0;
                        o.y += w * v1;
                        *p = o;
                    }
                }
            }
        }
}

// ---------------- launch ----------------
extern "C" void kernel_launch(void* const* d_in, const int* in_sizes, int n_in,
                              void* d_out, int out_size) {
    (void)in_sizes; (void)n_in; (void)out_size;
    const float* x = (const float*)d_in[0];
    const float* w_router = (const float*)d_in[1];
    const float* w_up = (const float*)d_in[2];
    const float* w_gate = (const float*)d_in[3];
    const float* w_down = (const float*)d_in[4];
    const float* ws_up = (const float*)d_in[5];
    const float* ws_gate = (const float*)d_in[6];
    const float* ws_down = (const float*)d_in[7];
    float* out = (float*)d_out;

    init_kernel<<<1, 32>>>();
    router_kernel<<<TT / 8, 256>>>(x, w_router);
    offsets_kernel<<<1, 32>>>();
    upgate_kernel<<<dim3(HIDX / 64, TT / 128, NEXP), 128>>>(x, w_up, w_gate, ws_up, ws_gate);
    down_kernel<<<dim3(DIMX / 128, TT / 128, 1), 128>>>(ws_down, out, 1);
    down_kernel<<<dim3(DIMX / 128, TT / 128, NR), 128>>>(w_down, out, 0);
}

// round 15
// speedup vs baseline: 1.5543x; 1.3228x over previous
#include <cuda_runtime.h>
#include <cuda_fp16.h>
#include <cstdint>
#include <cstring>

#define TT 2048
#define DIMX 1024
#define HIDX 4096
#define NEXP 8
#define NR 7
#define ALPHAF 2.0f

// ---------------- device scratch ----------------
__device__ int g_count[NEXP];
__device__ int g_offset[NR];
__device__ int g_list[NR * TT];
__device__ float g_wtok[TT];
__device__ __half g_hr[(size_t)TT * HIDX];
__device__ __half g_hs[(size_t)TT * HIDX];
// fp16 copies: experts 0..6 routed, slot 7 = shared expert
__device__ __half g_wu16[(size_t)NEXP * DIMX * HIDX];
__device__ __half g_wg16[(size_t)NEXP * DIMX * HIDX];
__device__ __half g_wd16[(size_t)NEXP * HIDX * DIMX];
__device__ __half g_x16[(size_t)TT * DIMX];

// ---------------- helpers ----------------
__device__ __forceinline__ uint32_t smem_u32(const void* p) {
    uint32_t a;
    asm("{ .reg .u64 t; cvta.to.shared.u64 t, %1; cvt.u32.u64 %0, t; }" : "=r"(a) : "l"(p));
    return a;
}
__device__ __forceinline__ void ldsm_x4(uint32_t* r, uint32_t addr) {
    asm volatile("ldmatrix.sync.aligned.m8n8.x4.shared.b16 {%0,%1,%2,%3}, [%4];"
                 : "=r"(r[0]), "=r"(r[1]), "=r"(r[2]), "=r"(r[3]) : "r"(addr));
}
__device__ __forceinline__ void ldsm_x2t(uint32_t* r, uint32_t addr) {
    asm volatile("ldmatrix.sync.aligned.m8n8.x2.trans.shared.b16 {%0,%1}, [%2];"
                 : "=r"(r[0]), "=r"(r[1]) : "r"(addr));
}
__device__ __forceinline__ void mma_f16(float* d, const uint32_t* a, const uint32_t* b) {
    asm volatile(
        "mma.sync.aligned.m16n8k16.row.col.f32.f16.f16.f32 "
        "{%0,%1,%2,%3}, {%4,%5,%6,%7}, {%8,%9}, {%0,%1,%2,%3};"
        : "+f"(d[0]), "+f"(d[1]), "+f"(d[2]), "+f"(d[3])
        : "r"(a[0]), "r"(a[1]), "r"(a[2]), "r"(a[3]), "r"(b[0]), "r"(b[1]));
}
__device__ __forceinline__ uint32_t h2_bits(__half2 h) {
    uint32_t u;
    memcpy(&u, &h, 4);
    return u;
}
__device__ __forceinline__ void cp16(uint32_t dst, const void* src) {
    asm volatile("cp.async.cg.shared.global [%0], [%1], 16;" :: "r"(dst), "l"(src));
}
#define CP_COMMIT() asm volatile("cp.async.commit_group;" ::: "memory")
#define CP_WAIT2()  asm volatile("cp.async.wait_group 2;" ::: "memory")

// ---------------- fp32 -> fp16 convert ----------------
__global__ void cvt_kernel(const float4* __restrict__ src, int which, size_t dst_off4, size_t n4) {
    __half* dbase = (which == 0) ? g_wu16 : (which == 1) ? g_wg16 : (which == 2) ? g_wd16 : g_x16;
    uint2* dst = reinterpret_cast<uint2*>(dbase) + dst_off4;
    size_t i = (size_t)blockIdx.x * blockDim.x + threadIdx.x;
    const size_t stride = (size_t)gridDim.x * blockDim.x;
    for (; i < n4; i += stride) {
        float4 v = src[i];
        uint2 o;
        o.x = h2_bits(__floats2half2_rn(v.x, v.y));
        o.y = h2_bits(__floats2half2_rn(v.z, v.w));
        dst[i] = o;
    }
}

// ---------------- small kernels ----------------
__global__ void init_kernel() {
    if (threadIdx.x < NEXP) g_count[threadIdx.x] = 0;
}

__global__ void router_kernel(const float* __restrict__ x, const float* __restrict__ wr) {
    __shared__ float sw[DIMX * NEXP];
    for (int i = threadIdx.x; i < DIMX * NEXP; i += blockDim.x) sw[i] = wr[i];
    __syncthreads();
    const int warp = threadIdx.x >> 5;
    const int lane = threadIdx.x & 31;
    const int tok = blockIdx.x * 8 + warp;
    if (tok >= TT) return;
    const float* xr = x + (size_t)tok * DIMX;
    float acc[NEXP];
#pragma unroll
    for (int e = 0; e < NEXP; ++e) acc[e] = 0.f;
    for (int k = lane; k < DIMX; k += 32) {
        float xv = xr[k];
#pragma unroll
        for (int e = 0; e < NEXP; ++e) acc[e] += xv * sw[k * NEXP + e];
    }
#pragma unroll
    for (int e = 0; e < NEXP; ++e)
#pragma unroll
        for (int o = 16; o; o >>= 1) acc[e] += __shfl_xor_sync(~0u, acc[e], o);
    if (lane == 0) {
        float m = acc[0];
        int idx = 0;
#pragma unroll
        for (int e = 1; e < NEXP; ++e)
            if (acc[e] > m) { m = acc[e]; idx = e; }
        float s = 0.f;
#pragma unroll
        for (int e = 0; e < NEXP; ++e) s += expf(acc[e] - m);
        g_wtok[tok] = ALPHAF / s;
        if (idx < NR) {
            int slot = atomicAdd(&g_count[idx], 1);
            g_list[idx * TT + slot] = tok;
        }
    }
}

__global__ void offsets_kernel() {
    if (threadIdx.x == 0) {
        int off = 0;
        for (int e = 0; e < NR; ++e) { g_offset[e] = off; off += g_count[e]; }
    }
}

// ---------------- upgate: cp.async fp16, 4-stage, fused SwiGLU ----------------
#define UPG_AS 24
#define UPG_BS 72
#define NST 4

__global__ __launch_bounds__(128) void upgate_kernel() {
    const int g = blockIdx.z;
    int n_rows, base;
    __half* H;
    const int* lst;
    if (g < NR) {
        n_rows = g_count[g];
        H = g_hr; base = g_offset[g]; lst = g_list + g * TT;
    } else {
        n_rows = TT; H = g_hs; base = 0; lst = nullptr;
    }
    const int m0 = blockIdx.y * 128;
    if (m0 >= n_rows) return;
    const int n0 = blockIdx.x * 64;
    const __half* Wu = g_wu16 + (size_t)g * DIMX * HIDX;
    const __half* Wg = g_wg16 + (size_t)g * DIMX * HIDX;

    __shared__ __half As[NST][128][UPG_AS];
    __shared__ __half BuS[NST][16][UPG_BS];
    __shared__ __half BgS[NST][16][UPG_BS];

    const int t = threadIdx.x;
    const int warp = t >> 5;
    const int lane = t & 31;
    const int wm = warp >> 1;
    const int wn = warp & 1;
    const int gid = lane >> 2;
    const int qp = lane & 3;

    // A producer: chunks t (row t>>1) and t+128 (row 64+(t>>1)), sub = (t&1)*8 halves
    const int ar0 = t >> 1, sub = (t & 1) * 8;
    int mm0 = m0 + ar0; if (mm0 >= n_rows) mm0 = n_rows - 1;
    int mm1 = m0 + 64 + ar0; if (mm1 >= n_rows) mm1 = n_rows - 1;
    const __half* aptr0 = g_x16 + (size_t)((g < NR) ? lst[mm0] : mm0) * DIMX + sub;
    const __half* aptr1 = g_x16 + (size_t)((g < NR) ? lst[mm1] : mm1) * DIMX + sub;
    const uint32_t adst0 = smem_u32(&As[0][ar0][sub]);
    const uint32_t adst1 = smem_u32(&As[0][64 + ar0][sub]);
    // B producer: row t>>3, col (t&7)*8
    const int bk = t >> 3, bn = (t & 7) * 8;
    const __half* buptr = Wu + (size_t)bk * HIDX + n0 + bn;
    const __half* bgptr = Wg + (size_t)bk * HIDX + n0 + bn;
    const uint32_t budst = smem_u32(&BuS[0][bk][bn]);
    const uint32_t bgdst = smem_u32(&BgS[0][bk][bn]);

    const uint32_t A_STG = 128 * UPG_AS * 2;
    const uint32_t B_STG = 16 * UPG_BS * 2;
    const int KT = DIMX / 16;  // 64

    // consumer base addresses (stage 0)
    const int lr = (lane & 7) + ((lane >> 3) & 1) * 8;
    const int lk = (lane >> 4) * 8;
    const uint32_t asb = smem_u32(As) + (uint32_t)(((wm * 64 + lr) * UPG_AS + lk) * 2);
    const int bl = lane & 15;
    const uint32_t bub = smem_u32(BuS) + (uint32_t)((bl * UPG_BS + wn * 32) * 2);
    const uint32_t bgb = smem_u32(BgS) + (uint32_t)((bl * UPG_BS + wn * 32) * 2);

    float accU[4][4][4], accG[4][4][4];
#pragma unroll
    for (int i = 0; i < 4; ++i)
#pragma unroll
        for (int j = 0; j < 4; ++j)
#pragma unroll
            for (int k = 0; k < 4; ++k) { accU[i][j][k] = 0.f; accG[i][j][k] = 0.f; }

    // prologue: stages 0..2
#pragma unroll
    for (int p = 0; p < NST - 1; ++p) {
        const int ko = p * 16;
        const size_t bo = (size_t)ko * HIDX;
        cp16(adst0 + p * A_STG, aptr0 + ko);
        cp16(adst1 + p * A_STG, aptr1 + ko);
        cp16(budst + p * B_STG, buptr + bo);
        cp16(bgdst + p * B_STG, bgptr + bo);
        CP_COMMIT();
    }

    for (int kt = 0; kt < KT; ++kt) {
        CP_WAIT2();
        __syncthreads();
        // issue stage kt+3
        {
            const int kn = kt + NST - 1;
            const int s = kn & (NST - 1);
            if (kn < KT) {
                const int ko = kn * 16;
                const size_t bo = (size_t)ko * HIDX;
                cp16(adst0 + s * A_STG, aptr0 + ko);
                cp16(adst1 + s * A_STG, aptr1 + ko);
                cp16(budst + s * B_STG, buptr + bo);
                cp16(bgdst + s * B_STG, bgptr + bo);
            }
            CP_COMMIT();
        }
        // compute stage kt%4
        const int s = kt & (NST - 1);
        uint32_t a[4][4], bu[4][2], bg[4][2];
        const uint32_t sa = asb + (uint32_t)s * A_STG;
        const uint32_t su = bub + (uint32_t)s * B_STG;
        const uint32_t sg = bgb + (uint32_t)s * B_STG;
#pragma unroll
        for (int mf = 0; mf < 4; ++mf) ldsm_x4(a[mf], sa + (uint32_t)(mf * 16 * UPG_AS * 2));
#pragma unroll
        for (int nf = 0; nf < 4; ++nf) {
            ldsm_x2t(bu[nf], su + (uint32_t)(nf * 8 * 2));
            ldsm_x2t(bg[nf], sg + (uint32_t)(nf * 8 * 2));
        }
#pragma unroll
        for (int mf = 0; mf < 4; ++mf)
#pragma unroll
            for (int nf = 0; nf < 4; ++nf) {
                mma_f16(accU[mf][nf], a[mf], bu[nf]);
                mma_f16(accG[mf][nf], a[mf], bg[nf]);
            }
        __syncthreads();
    }

    // epilogue: h = up * silu(gate) -> fp16
#pragma unroll
    for (int mf = 0; mf < 4; ++mf)
#pragma unroll
        for (int nf = 0; nf < 4; ++nf) {
            const int col = n0 + wn * 32 + nf * 8 + qp * 2;
#pragma unroll
            for (int half = 0; half < 2; ++half) {
                const int m = m0 + wm * 64 + mf * 16 + gid + half * 8;
                if (m < n_rows) {
                    float u0 = accU[mf][nf][half * 2 + 0];
                    float u1 = accU[mf][nf][half * 2 + 1];
                    float gv0 = accG[mf][nf][half * 2 + 0];
                    float gv1 = accG[mf][nf][half * 2 + 1];
                    float h0 = u0 * (gv0 / (1.f + expf(-gv0)));
                    float h1 = u1 * (gv1 / (1.f + expf(-gv1)));
                    __half2 hv = __floats2half2_rn(h0, h1);
                    *(__half2*)(H + (size_t)(base + m) * HIDX + col) = hv;
                }
            }
        }
}

// ---------------- down: cp.async fp16, 4-stage ----------------
#define DWN_AS 24
#define DWN_BS 136

__global__ __launch_bounds__(128) void down_kernel(float* __restrict__ out, int shared_mode) {
    int n_rows, base;
    const __half* Wd;
    const __half* Hsrc;
    const int* lst;
    if (shared_mode) {
        n_rows = TT; Wd = g_wd16 + (size_t)NR * HIDX * DIMX; Hsrc = g_hs; base = 0; lst = nullptr;
    } else {
        const int g = blockIdx.z;
        n_rows = g_count[g];
        Wd = g_wd16 + (size_t)g * HIDX * DIMX;
        Hsrc = g_hr; base = g_offset[g]; lst = g_list + g * TT;
    }
    const int m0 = blockIdx.y * 128;
    if (m0 >= n_rows) return;
    const int n0 = blockIdx.x * 128;

    __shared__ __half As[NST][128][DWN_AS];
    __shared__ __half Bs[NST][16][DWN_BS];

    const int t = threadIdx.x;
    const int warp = t >> 5;
    const int lane = t & 31;
    const int wm = warp >> 1;
    const int wn = warp & 1;
    const int gid = lane >> 2;
    const int qp = lane & 3;

    const int ar0 = t >> 1, sub = (t & 1) * 8;
    int mm0 = m0 + ar0; if (mm0 >= n_rows) mm0 = n_rows - 1;
    int mm1 = m0 + 64 + ar0; if (mm1 >= n_rows) mm1 = n_rows - 1;
    const __half* aptr0 = Hsrc + (size_t)(base + mm0) * HIDX + sub;
    const __half* aptr1 = Hsrc + (size_t)(base + mm1) * HIDX + sub;
    const uint32_t adst0 = smem_u32(&As[0][ar0][sub]);
    const uint32_t adst1 = smem_u32(&As[0][64 + ar0][sub]);
    // B: chunks t (rows 0..7) and t+128 (rows 8..15); row = chunk>>4, col = (chunk&15)*8
    const int brow0 = t >> 4, brow1 = 8 + (t >> 4), bcol = (t & 15) * 8;
    const __half* bptr0 = Wd + (size_t)brow0 * DIMX + n0 + bcol;
    const __half* bptr1 = Wd + (size_t)brow1 * DIMX + n0 + bcol;
    const uint32_t bdst0 = smem_u32(&Bs[0][brow0][bcol]);
    const uint32_t bdst1 = smem_u32(&Bs[0][brow1][bcol]);

    const uint32_t A_STG = 128 * DWN_AS * 2;
    const uint32_t B_STG = 16 * DWN_BS * 2;
    const int KT = HIDX / 16;  // 256

    const int lr = (lane & 7) + ((lane >> 3) & 1) * 8;
    const int lk = (lane >> 4) * 8;
    const uint32_t asb = smem_u32(As) + (uint32_t)(((wm * 64 + lr) * DWN_AS + lk) * 2);
    const int bl = lane & 15;
    const uint32_t bsb = smem_u32(Bs) + (uint32_t)((bl * DWN_BS + wn * 64) * 2);

    float acc[4][8][4];
#pragma unroll
    for (int i = 0; i < 4; ++i)
#pragma unroll
        for (int j = 0; j < 8; ++j)
#pragma unroll
            for (int k = 0; k < 4; ++k) acc[i][j][k] = 0.f;

#pragma unroll
    for (int p = 0; p < NST - 1; ++p) {
        const int ko = p * 16;
        const size_t bo = (size_t)ko * DIMX;
        cp16(adst0 + p * A_STG, aptr0 + ko);
        cp16(adst1 + p * A_STG, aptr1 + ko);
        cp16(bdst0 + p * B_STG, bptr0 + bo);
        cp16(bdst1 + p * B_STG, bptr1 + bo);
        CP_COMMIT();
    }

    for (int kt = 0; kt < KT; ++kt) {
        CP_WAIT2();
        __syncthreads();
        {
            const int kn = kt + NST - 1;
            const int s = kn & (NST - 1);
            if (kn < KT) {
                const int ko = kn * 16;
                const size_t bo = (size_t)ko * DIMX;
                cp16(adst0 + s * A_STG, aptr0 + ko);
                cp16(adst1 + s * A_STG, aptr1 + ko);
                cp16(bdst0 + s * B_STG, bptr0 + bo);
                cp16(bdst1 + s * B_STG, bptr1 + bo);
            }
            CP_COMMIT();
        }
        const int s = kt & (NST - 1);
        uint32_t a[4][4], b[8][2];
        const uint32_t sa = asb + (uint32_t)s * A_STG;
        const uint32_t sbv = bsb + (uint32_t)s * B_STG;
#pragma unroll
        for (int mf = 0; mf < 4; ++mf) ldsm_x4(a[mf], sa + (uint32_t)(mf * 16 * DWN_AS * 2));
#pragma unroll
        for (int nf = 0; nf < 8; ++nf) ldsm_x2t(b[nf], sbv + (uint32_t)(nf * 8 * 2));
#pragma unroll
        for (int mf = 0; mf < 4; ++mf)
#pragma unroll
            for (int nf = 0; nf < 8; ++nf) mma_f16(acc[mf][nf], a[mf], b[nf]);
        __syncthreads();
    }

#pragma unroll
    for (int mf = 0; mf < 4; ++mf)
#pragma unroll
        for (int nf = 0; nf < 8; ++nf) {
            const int col = n0 + wn * 64 + nf * 8 + qp * 2;
#pragma unroll
            for (int half = 0; half < 2; ++half) {
                const int m = m0 + wm * 64 + mf * 16 + gid + half * 8;
                if (m < n_rows) {
                    float v0 = acc[mf][nf][half * 2 + 0];
                    float v1 = acc[mf][nf][half * 2 + 1];
                    if (shared_mode) {
                        *(float2*)(out + (size_t)m * DIMX + col) = make_float2(v0, v1);
                    } else {
                        const int tok = lst[m];
                        const float w = g_wtok[tok];
                        float2* p = (float2*)(out + (size_t)tok * DIMX + col);
                        float2 o = *p;
                        o.x += w * v0;
                        o.y += w * v1;
                        *p = o;
                    }
                }
            }
        }
}

// ---------------- launch ----------------
extern "C" void kernel_launch(void* const* d_in, const int* in_sizes, int n_in,
                              void* d_out, int out_size) {
    (void)in_sizes; (void)n_in; (void)out_size;
    const float* x = (const float*)d_in[0];
    const float* w_router = (const float*)d_in[1];
    const float* w_up = (const float*)d_in[2];
    const float* w_gate = (const float*)d_in[3];
    const float* w_down = (const float*)d_in[4];
    const float* ws_up = (const float*)d_in[5];
    const float* ws_gate = (const float*)d_in[6];
    const float* ws_down = (const float*)d_in[7];
    float* out = (float*)d_out;

    const size_t WE4 = (size_t)DIMX * HIDX / 4;       // per-expert float4 count
    const size_t W7_4 = (size_t)NR * DIMX * HIDX / 4; // 7 experts

    init_kernel<<<1, 32>>>();
    router_kernel<<<TT / 8, 256>>>(x, w_router);
    offsets_kernel<<<1, 32>>>();
    // fp32 -> fp16 conversions
    cvt_kernel<<<4096, 256>>>((const float4*)w_up,    0, 0,        W7_4);
    cvt_kernel<<<1024, 256>>>((const float4*)ws_up,   0, NR * WE4, WE4);
    cvt_kernel<<<4096, 256>>>((const float4*)w_gate,  1, 0,        W7_4);
    cvt_kernel<<<1024, 256>>>((const float4*)ws_gate, 1, NR * WE4, WE4);
    cvt_kernel<<<4096, 256>>>((const float4*)w_down,  2, 0,        W7_4);
    cvt_kernel<<<1024, 256>>>((const float4*)ws_down, 2, NR * WE4, WE4);
    cvt_kernel<<<512, 256>>>((const float4*)x,        3, 0, (size_t)TT * DIMX / 4);

    upgate_kernel<<<dim3(HIDX / 64, TT / 128, NEXP), 128>>>();
    down_kernel<<<dim3(DIMX / 128, TT / 128, 1), 128>>>(out, 1);
    down_kernel<<<dim3(DIMX / 128, TT / 128, NR), 128>>>(out, 0);
}

// round 16
// speedup vs baseline: 1.5941x; 1.0256x over previous
#include <cuda_runtime.h>
#include <cuda_fp16.h>
#include <cstdint>
#include <cstring>

#define TT 2048
#define DIMX 1024
#define HIDX 4096
#define NEXP 8
#define NR 7
#define ALPHAF 2.0f

// ---------------- device scratch ----------------
__device__ int g_count[NEXP];
__device__ int g_offset[NR];
__device__ int g_list[NR * TT];
__device__ float g_wtok[TT];
__device__ __half g_hr[(size_t)TT * HIDX];
__device__ __half g_hs[(size_t)TT * HIDX];
__device__ __half g_wu16[(size_t)NEXP * DIMX * HIDX];
__device__ __half g_wg16[(size_t)NEXP * DIMX * HIDX];
__device__ __half g_wd16[(size_t)NEXP * HIDX * DIMX];
__device__ __half g_x16[(size_t)TT * DIMX];

// ---------------- helpers ----------------
__device__ __forceinline__ uint32_t smem_u32(const void* p) {
    uint32_t a;
    asm("{ .reg .u64 t; cvta.to.shared.u64 t, %1; cvt.u32.u64 %0, t; }" : "=r"(a) : "l"(p));
    return a;
}
__device__ __forceinline__ void ldsm_x4(uint32_t* r, uint32_t addr) {
    asm volatile("ldmatrix.sync.aligned.m8n8.x4.shared.b16 {%0,%1,%2,%3}, [%4];"
                 : "=r"(r[0]), "=r"(r[1]), "=r"(r[2]), "=r"(r[3]) : "r"(addr));
}
__device__ __forceinline__ void ldsm_x2t(uint32_t* r, uint32_t addr) {
    asm volatile("ldmatrix.sync.aligned.m8n8.x2.trans.shared.b16 {%0,%1}, [%2];"
                 : "=r"(r[0]), "=r"(r[1]) : "r"(addr));
}
__device__ __forceinline__ void mma_f16(float* d, const uint32_t* a, const uint32_t* b) {
    asm volatile(
        "mma.sync.aligned.m16n8k16.row.col.f32.f16.f16.f32 "
        "{%0,%1,%2,%3}, {%4,%5,%6,%7}, {%8,%9}, {%0,%1,%2,%3};"
        : "+f"(d[0]), "+f"(d[1]), "+f"(d[2]), "+f"(d[3])
        : "r"(a[0]), "r"(a[1]), "r"(a[2]), "r"(a[3]), "r"(b[0]), "r"(b[1]));
}
__device__ __forceinline__ uint32_t h2_bits(__half2 h) {
    uint32_t u;
    memcpy(&u, &h, 4);
    return u;
}
__device__ __forceinline__ void cp16(uint32_t dst, const void* src) {
    asm volatile("cp.async.cg.shared.global [%0], [%1], 16;" :: "r"(dst), "l"(src));
}
#define CP_COMMIT() asm volatile("cp.async.commit_group;" ::: "memory")
#define CP_WAIT2()  asm volatile("cp.async.wait_group 2;" ::: "memory")

// ---------------- fp32 -> fp16 convert ----------------
__global__ void cvt_kernel(const float4* __restrict__ src, int which, size_t dst_off4, size_t n4) {
    __half* dbase = (which == 0) ? g_wu16 : (which == 1) ? g_wg16 : (which == 2) ? g_wd16 : g_x16;
    uint2* dst = reinterpret_cast<uint2*>(dbase) + dst_off4;
    size_t i = (size_t)blockIdx.x * blockDim.x + threadIdx.x;
    const size_t stride = (size_t)gridDim.x * blockDim.x;
    for (; i < n4; i += stride) {
        float4 v = src[i];
        uint2 o;
        o.x = h2_bits(__floats2half2_rn(v.x, v.y));
        o.y = h2_bits(__floats2half2_rn(v.z, v.w));
        dst[i] = o;
    }
}

// ---------------- small kernels ----------------
__global__ void init_kernel() {
    if (threadIdx.x < NEXP) g_count[threadIdx.x] = 0;
}

__global__ void router_kernel(const float* __restrict__ x, const float* __restrict__ wr) {
    __shared__ float sw[DIMX * NEXP];
    for (int i = threadIdx.x; i < DIMX * NEXP; i += blockDim.x) sw[i] = wr[i];
    __syncthreads();
    const int warp = threadIdx.x >> 5;
    const int lane = threadIdx.x & 31;
    const int tok = blockIdx.x * 8 + warp;
    if (tok >= TT) return;
    const float* xr = x + (size_t)tok * DIMX;
    float acc[NEXP];
#pragma unroll
    for (int e = 0; e < NEXP; ++e) acc[e] = 0.f;
    for (int k = lane; k < DIMX; k += 32) {
        float xv = xr[k];
#pragma unroll
        for (int e = 0; e < NEXP; ++e) acc[e] += xv * sw[k * NEXP + e];
    }
#pragma unroll
    for (int e = 0; e < NEXP; ++e)
#pragma unroll
        for (int o = 16; o; o >>= 1) acc[e] += __shfl_xor_sync(~0u, acc[e], o);
    if (lane == 0) {
        float m = acc[0];
        int idx = 0;
#pragma unroll
        for (int e = 1; e < NEXP; ++e)
            if (acc[e] > m) { m = acc[e]; idx = e; }
        float s = 0.f;
#pragma unroll
        for (int e = 0; e < NEXP; ++e) s += expf(acc[e] - m);
        g_wtok[tok] = ALPHAF / s;
        if (idx < NR) {
            int slot = atomicAdd(&g_count[idx], 1);
            g_list[idx * TT + slot] = tok;
        }
    }
}

__global__ void offsets_kernel() {
    if (threadIdx.x == 0) {
        int off = 0;
        for (int e = 0; e < NR; ++e) { g_offset[e] = off; off += g_count[e]; }
    }
}

// ---------------- upgate: 256 thr, warps 2m x 4n, fused SwiGLU ----------------
#define UPG_AS 24
#define UPG_BS 72
#define NST 4

__global__ __launch_bounds__(256, 2) void upgate_kernel() {
    const int g = blockIdx.z;
    int n_rows, base;
    __half* H;
    const int* lst;
    if (g < NR) {
        n_rows = g_count[g];
        H = g_hr; base = g_offset[g]; lst = g_list + g * TT;
    } else {
        n_rows = TT; H = g_hs; base = 0; lst = nullptr;
    }
    const int m0 = blockIdx.y * 128;
    if (m0 >= n_rows) return;
    const int n0 = blockIdx.x * 64;
    const __half* Wu = g_wu16 + (size_t)g * DIMX * HIDX;
    const __half* Wg = g_wg16 + (size_t)g * DIMX * HIDX;

    __shared__ __half As[NST][128][UPG_AS];
    __shared__ __half BuS[NST][16][UPG_BS];
    __shared__ __half BgS[NST][16][UPG_BS];

    const int t = threadIdx.x;
    const int warp = t >> 5;
    const int lane = t & 31;
    const int wm = warp >> 2;   // 0..1
    const int wn = warp & 3;    // 0..3
    const int gid = lane >> 2;
    const int qp = lane & 3;

    // A producer: 1 chunk/thread: row t>>1, sub (t&1)*8
    const int ar0 = t >> 1, sub = (t & 1) * 8;
    int mm0 = m0 + ar0; if (mm0 >= n_rows) mm0 = n_rows - 1;
    const __half* aptr0 = g_x16 + (size_t)((g < NR) ? lst[mm0] : mm0) * DIMX + sub;
    const uint32_t adst0 = smem_u32(&As[0][ar0][sub]);
    // B producer: threads 0..127 -> Bu, 128..255 -> Bg; chunk c = t&127: row c>>3, col (c&7)*8
    const int c = t & 127;
    const int bk = c >> 3, bn = (c & 7) * 8;
    const bool isBu = (t < 128);
    const __half* bptr = (isBu ? Wu : Wg) + (size_t)bk * HIDX + n0 + bn;
    const uint32_t bdst = smem_u32(isBu ? &BuS[0][bk][bn] : &BgS[0][bk][bn]);

    const uint32_t A_STG = 128 * UPG_AS * 2;
    const uint32_t B_STG = 16 * UPG_BS * 2;
    const int KT = DIMX / 16;  // 64

    // consumer base addresses
    const int lr = (lane & 7) + ((lane >> 3) & 1) * 8;
    const int lk = (lane >> 4) * 8;
    const uint32_t asb = smem_u32(As) + (uint32_t)(((wm * 64 + lr) * UPG_AS + lk) * 2);
    const int bl = lane & 15;
    const uint32_t bub = smem_u32(BuS) + (uint32_t)((bl * UPG_BS + wn * 16) * 2);
    const uint32_t bgb = smem_u32(BgS) + (uint32_t)((bl * UPG_BS + wn * 16) * 2);

    float accU[4][2][4], accG[4][2][4];
#pragma unroll
    for (int i = 0; i < 4; ++i)
#pragma unroll
        for (int j = 0; j < 2; ++j)
#pragma unroll
            for (int k = 0; k < 4; ++k) { accU[i][j][k] = 0.f; accG[i][j][k] = 0.f; }

#pragma unroll
    for (int p = 0; p < NST - 1; ++p) {
        const int ko = p * 16;
        cp16(adst0 + p * A_STG, aptr0 + ko);
        cp16(bdst + p * B_STG, bptr + (size_t)ko * HIDX);
        CP_COMMIT();
    }

    for (int kt = 0; kt < KT; ++kt) {
        CP_WAIT2();
        __syncthreads();
        {
            const int kn = kt + NST - 1;
            const int s = kn & (NST - 1);
            if (kn < KT) {
                const int ko = kn * 16;
                cp16(adst0 + s * A_STG, aptr0 + ko);
                cp16(bdst + s * B_STG, bptr + (size_t)ko * HIDX);
            }
            CP_COMMIT();
        }
        const int s = kt & (NST - 1);
        uint32_t a[4][4], bu[2][2], bg[2][2];
        const uint32_t sa = asb + (uint32_t)s * A_STG;
        const uint32_t su = bub + (uint32_t)s * B_STG;
        const uint32_t sg = bgb + (uint32_t)s * B_STG;
#pragma unroll
        for (int mf = 0; mf < 4; ++mf) ldsm_x4(a[mf], sa + (uint32_t)(mf * 16 * UPG_AS * 2));
#pragma unroll
        for (int nf = 0; nf < 2; ++nf) {
            ldsm_x2t(bu[nf], su + (uint32_t)(nf * 8 * 2));
            ldsm_x2t(bg[nf], sg + (uint32_t)(nf * 8 * 2));
        }
#pragma unroll
        for (int mf = 0; mf < 4; ++mf)
#pragma unroll
            for (int nf = 0; nf < 2; ++nf) {
                mma_f16(accU[mf][nf], a[mf], bu[nf]);
                mma_f16(accG[mf][nf], a[mf], bg[nf]);
            }
        __syncthreads();
    }

    // epilogue: h = up * silu(gate) -> fp16
#pragma unroll
    for (int mf = 0; mf < 4; ++mf)
#pragma unroll
        for (int nf = 0; nf < 2; ++nf) {
            const int col = n0 + wn * 16 + nf * 8 + qp * 2;
#pragma unroll
            for (int half = 0; half < 2; ++half) {
                const int m = m0 + wm * 64 + mf * 16 + gid + half * 8;
                if (m < n_rows) {
                    float u0 = accU[mf][nf][half * 2 + 0];
                    float u1 = accU[mf][nf][half * 2 + 1];
                    float gv0 = accG[mf][nf][half * 2 + 0];
                    float gv1 = accG[mf][nf][half * 2 + 1];
                    float h0 = u0 * (gv0 / (1.f + expf(-gv0)));
                    float h1 = u1 * (gv1 / (1.f + expf(-gv1)));
                    __half2 hv = __floats2half2_rn(h0, h1);
                    *(__half2*)(H + (size_t)(base + m) * HIDX + col) = hv;
                }
            }
        }
}

// ---------------- down: 256 thr, warps 2m x 4n ----------------
#define DWN_AS 24
#define DWN_BS 136

__global__ __launch_bounds__(256, 2) void down_kernel(float* __restrict__ out, int shared_mode) {
    int n_rows, base;
    const __half* Wd;
    const __half* Hsrc;
    const int* lst;
    if (shared_mode) {
        n_rows = TT; Wd = g_wd16 + (size_t)NR * HIDX * DIMX; Hsrc = g_hs; base = 0; lst = nullptr;
    } else {
        const int g = blockIdx.z;
        n_rows = g_count[g];
        Wd = g_wd16 + (size_t)g * HIDX * DIMX;
        Hsrc = g_hr; base = g_offset[g]; lst = g_list + g * TT;
    }
    const int m0 = blockIdx.y * 128;
    if (m0 >= n_rows) return;
    const int n0 = blockIdx.x * 128;

    __shared__ __half As[NST][128][DWN_AS];
    __shared__ __half Bs[NST][16][DWN_BS];

    const int t = threadIdx.x;
    const int warp = t >> 5;
    const int lane = t & 31;
    const int wm = warp >> 2;
    const int wn = warp & 3;
    const int gid = lane >> 2;
    const int qp = lane & 3;

    const int ar0 = t >> 1, sub = (t & 1) * 8;
    int mm0 = m0 + ar0; if (mm0 >= n_rows) mm0 = n_rows - 1;
    const __half* aptr0 = Hsrc + (size_t)(base + mm0) * HIDX + sub;
    const uint32_t adst0 = smem_u32(&As[0][ar0][sub]);
    // B: 256 chunks: row t>>4, col (t&15)*8
    const int brow = t >> 4, bcol = (t & 15) * 8;
    const __half* bptr = Wd + (size_t)brow * DIMX + n0 + bcol;
    const uint32_t bdst = smem_u32(&Bs[0][brow][bcol]);

    const uint32_t A_STG = 128 * DWN_AS * 2;
    const uint32_t B_STG = 16 * DWN_BS * 2;
    const int KT = HIDX / 16;  // 256

    const int lr = (lane & 7) + ((lane >> 3) & 1) * 8;
    const int lk = (lane >> 4) * 8;
    const uint32_t asb = smem_u32(As) + (uint32_t)(((wm * 64 + lr) * DWN_AS + lk) * 2);
    const int bl = lane & 15;
    const uint32_t bsb = smem_u32(Bs) + (uint32_t)((bl * DWN_BS + wn * 32) * 2);

    float acc[4][4][4];
#pragma unroll
    for (int i = 0; i < 4; ++i)
#pragma unroll
        for (int j = 0; j < 4; ++j)
#pragma unroll
            for (int k = 0; k < 4; ++k) acc[i][j][k] = 0.f;

#pragma unroll
    for (int p = 0; p < NST - 1; ++p) {
        const int ko = p * 16;
        cp16(adst0 + p * A_STG, aptr0 + ko);
        cp16(bdst + p * B_STG, bptr + (size_t)ko * DIMX);
        CP_COMMIT();
    }

    for (int kt = 0; kt < KT; ++kt) {
        CP_WAIT2();
        __syncthreads();
        {
            const int kn = kt + NST - 1;
            const int s = kn & (NST - 1);
            if (kn < KT) {
                const int ko = kn * 16;
                cp16(adst0 + s * A_STG, aptr0 + ko);
                cp16(bdst + s * B_STG, bptr + (size_t)ko * DIMX);
            }
            CP_COMMIT();
        }
        const int s = kt & (NST - 1);
        uint32_t a[4][4], b[4][2];
        const uint32_t sa = asb + (uint32_t)s * A_STG;
        const uint32_t sbv = bsb + (uint32_t)s * B_STG;
#pragma unroll
        for (int mf = 0; mf < 4; ++mf) ldsm_x4(a[mf], sa + (uint32_t)(mf * 16 * DWN_AS * 2));
#pragma unroll
        for (int nf = 0; nf < 4; ++nf) ldsm_x2t(b[nf], sbv + (uint32_t)(nf * 8 * 2));
#pragma unroll
        for (int mf = 0; mf < 4; ++mf)
#pragma unroll
            for (int nf = 0; nf < 4; ++nf) mma_f16(acc[mf][nf], a[mf], b[nf]);
        __syncthreads();
    }

#pragma unroll
    for (int mf = 0; mf < 4; ++mf)
#pragma unroll
        for (int nf = 0; nf < 4; ++nf) {
            const int col = n0 + wn * 32 + nf * 8 + qp * 2;
#pragma unroll
            for (int half = 0; half < 2; ++half) {
                const int m = m0 + wm * 64 + mf * 16 + gid + half * 8;
                if (m < n_rows) {
                    float v0 = acc[mf][nf][half * 2 + 0];
                    float v1 = acc[mf][nf][half * 2 + 1];
                    if (shared_mode) {
                        *(float2*)(out + (size_t)m * DIMX + col) = make_float2(v0, v1);
                    } else {
                        const int tok = lst[m];
                        const float w = g_wtok[tok];
                        float2* p = (float2*)(out + (size_t)tok * DIMX + col);
                        float2 o = *p;
                        o.x += w * v0;
                        o.y += w * v1;
                        *p = o;
                    }
                }
            }
        }
}

// ---------------- launch ----------------
extern "C" void kernel_launch(void* const* d_in, const int* in_sizes, int n_in,
                              void* d_out, int out_size) {
    (void)in_sizes; (void)n_in; (void)out_size;
    const float* x = (const float*)d_in[0];
    const float* w_router = (const float*)d_in[1];
    const float* w_up = (const float*)d_in[2];
    const float* w_gate = (const float*)d_in[3];
    const float* w_down = (const float*)d_in[4];
    const float* ws_up = (const float*)d_in[5];
    const float* ws_gate = (const float*)d_in[6];
    const float* ws_down = (const float*)d_in[7];
    float* out = (float*)d_out;

    const size_t WE4 = (size_t)DIMX * HIDX / 4;
    const size_t W7_4 = (size_t)NR * DIMX * HIDX / 4;

    init_kernel<<<1, 32>>>();
    router_kernel<<<TT / 8, 256>>>(x, w_router);
    offsets_kernel<<<1, 32>>>();
    cvt_kernel<<<4096, 256>>>((const float4*)w_up,    0, 0,        W7_4);
    cvt_kernel<<<1024, 256>>>((const float4*)ws_up,   0, NR * WE4, WE4);
    cvt_kernel<<<4096, 256>>>((const float4*)w_gate,  1, 0,        W7_4);
    cvt_kernel<<<1024, 256>>>((const float4*)ws_gate, 1, NR * WE4, WE4);
    cvt_kernel<<<4096, 256>>>((const float4*)w_down,  2, 0,        W7_4);
    cvt_kernel<<<1024, 256>>>((const float4*)ws_down, 2, NR * WE4, WE4);
    cvt_kernel<<<512, 256>>>((const float4*)x,        3, 0, (size_t)TT * DIMX / 4);

    upgate_kernel<<<dim3(HIDX / 64, TT / 128, NEXP), 256>>>();
    down_kernel<<<dim3(DIMX / 128, TT / 128, 1), 256>>>(out, 1);
    down_kernel<<<dim3(DIMX / 128, TT / 128, NR), 256>>>(out, 0);
}